// round 9
// baseline (speedup 1.0000x reference)
#include <cuda_runtime.h>
#include <math.h>
#include <stdint.h>

#define NB 16
#define NC 512
#define NHW 1024
#define NHEADS 8
#define HD 64
#define NG 32
#define OC3 1536
#define GN_EPS 1e-5f

typedef unsigned short ushort_t;

// Scratch (static device globals — allocation-free per harness rules)
__device__ ushort_t g_wqhi[(size_t)OC3 * NC];
__device__ ushort_t g_wqlo[(size_t)OC3 * NC];
__device__ ushort_t g_wphi[(size_t)NC * NC];
__device__ ushort_t g_wplo[(size_t)NC * NC];
__device__ ushort_t g_xnhi[(size_t)NB * NC * NHW];
__device__ ushort_t g_xnlo[(size_t)NB * NC * NHW];
__device__ ushort_t g_qkvhi[(size_t)NB * OC3 * NHW];
__device__ ushort_t g_qkvlo[(size_t)NB * OC3 * NHW];
__device__ ushort_t g_atthi[(size_t)NB * NC * NHW];
__device__ ushort_t g_attlo[(size_t)NB * NC * NHW];

// ============================ helpers ======================================
__device__ __forceinline__ uint32_t smem_u32(const void* p) {
  uint32_t a;
  asm("{ .reg .u64 t; cvta.to.shared.u64 t, %1; cvt.u32.u64 %0, t; }"
      : "=r"(a) : "l"(p));
  return a;
}
__device__ __forceinline__ uint32_t packbf2(float lo16, float hi16) {
  uint32_t r;
  asm("cvt.rn.bf16x2.f32 %0, %1, %2;" : "=r"(r) : "f"(hi16), "f"(lo16));
  return r;
}
__device__ __forceinline__ float bflo_f(uint32_t u) {
  return __uint_as_float(u << 16);
}
__device__ __forceinline__ float bfhi_f(uint32_t u) {
  return __uint_as_float(u & 0xffff0000u);
}
__device__ __forceinline__ void ldsm_x4(uint32_t* r, uint32_t addr) {
  asm volatile("ldmatrix.sync.aligned.m8n8.x4.shared.b16 {%0,%1,%2,%3}, [%4];"
               : "=r"(r[0]), "=r"(r[1]), "=r"(r[2]), "=r"(r[3]) : "r"(addr));
}
__device__ __forceinline__ void ldsm_x4_t(uint32_t* r, uint32_t addr) {
  asm volatile(
      "ldmatrix.sync.aligned.m8n8.x4.trans.shared.b16 {%0,%1,%2,%3}, [%4];"
      : "=r"(r[0]), "=r"(r[1]), "=r"(r[2]), "=r"(r[3]) : "r"(addr));
}
__device__ __forceinline__ void mma16816(float* d, const uint32_t* a,
                                         const uint32_t* b) {
  asm volatile(
      "mma.sync.aligned.m16n8k16.row.col.f32.bf16.bf16.f32 "
      "{%0,%1,%2,%3}, {%4,%5,%6,%7}, {%8,%9}, {%0,%1,%2,%3};"
      : "+f"(d[0]), "+f"(d[1]), "+f"(d[2]), "+f"(d[3])
      : "r"(a[0]), "r"(a[1]), "r"(a[2]), "r"(a[3]), "r"(b[0]), "r"(b[1]));
}

// ---------------------------------------------------------------------------
// Weight prep: fp32 -> hi/lo bf16 planes (once per launch)
// ---------------------------------------------------------------------------
__global__ void __launch_bounds__(256) prep_w_kernel(
    const float* __restrict__ qkv_w, const float* __restrict__ proj_w) {
  const int idx = blockIdx.x * 256 + threadIdx.x;
  const int nq = OC3 * NC / 4;
  const float* src;
  ushort_t *dh, *dl;
  int off;
  if (idx < nq) {
    src = qkv_w; dh = g_wqhi; dl = g_wqlo; off = idx * 4;
  } else {
    src = proj_w; dh = g_wphi; dl = g_wplo; off = (idx - nq) * 4;
  }
  float4 v = *(const float4*)(src + off);
  uint32_t h01 = packbf2(v.x, v.y), h23 = packbf2(v.z, v.w);
  uint32_t l01 = packbf2(v.x - bflo_f(h01), v.y - bfhi_f(h01));
  uint32_t l23 = packbf2(v.z - bflo_f(h23), v.w - bfhi_f(h23));
  *(uint2*)(dh + off) = make_uint2(h01, h23);
  *(uint2*)(dl + off) = make_uint2(l01, l23);
}

// ---------------------------------------------------------------------------
// GroupNorm -> hi/lo bf16 planes
// ---------------------------------------------------------------------------
__global__ void __launch_bounds__(256) gn_kernel(
    const float* __restrict__ x, const float* __restrict__ gamma,
    const float* __restrict__ beta) {
  const int bg = blockIdx.x;
  const int g = bg & (NG - 1);
  const size_t base = (size_t)bg * (NC / NG) * NHW;
  const float* px = x + base;
  ushort_t* poh = g_xnhi + base;
  ushort_t* pol = g_xnlo + base;
  const int tid = threadIdx.x;

  float s = 0.f, q = 0.f;
#pragma unroll
  for (int k = 0; k < 16; k++) {
    float4 v = *(const float4*)(px + (size_t)(tid + k * 256) * 4);
    s += v.x + v.y + v.z + v.w;
    q += v.x * v.x + v.y * v.y + v.z * v.z + v.w * v.w;
  }
#pragma unroll
  for (int off = 16; off; off >>= 1) {
    s += __shfl_xor_sync(0xffffffffu, s, off);
    q += __shfl_xor_sync(0xffffffffu, q, off);
  }
  __shared__ float ss[8], sq[8];
  __shared__ float s_mean, s_inv;
  const int w = tid >> 5;
  if ((tid & 31) == 0) { ss[w] = s; sq[w] = q; }
  __syncthreads();
  if (tid == 0) {
    float ts = 0.f, tq = 0.f;
#pragma unroll
    for (int i = 0; i < 8; i++) { ts += ss[i]; tq += sq[i]; }
    float mean = ts * (1.f / 16384.f);
    float var = tq * (1.f / 16384.f) - mean * mean;
    s_mean = mean;
    s_inv = rsqrtf(var + GN_EPS);
  }
  __syncthreads();
  const float mean = s_mean, inv = s_inv;
#pragma unroll
  for (int k = 0; k < 16; k++) {
    size_t off = (size_t)(tid + k * 256) * 4;
    int c = g * 16 + (int)(off >> 10);
    float ga = gamma[c], be = beta[c];
    float4 v = *(const float4*)(px + off);
    v.x = (v.x - mean) * inv * ga + be;
    v.y = (v.y - mean) * inv * ga + be;
    v.z = (v.z - mean) * inv * ga + be;
    v.w = (v.w - mean) * inv * ga + be;
    uint32_t h01 = packbf2(v.x, v.y), h23 = packbf2(v.z, v.w);
    uint32_t l01 = packbf2(v.x - bflo_f(h01), v.y - bfhi_f(h01));
    uint32_t l23 = packbf2(v.z - bflo_f(h23), v.w - bfhi_f(h23));
    *(uint2*)(poh + off) = make_uint2(h01, h23);
    *(uint2*)(pol + off) = make_uint2(l01, l23);
  }
}

// ---------------------------------------------------------------------------
// bf16 GEMM (3-term split) with register prefetch of the next K-chunk.
// Tile 128(o) x 128(t), K-chunk 32; 8 warps = 4m x 2n; warp 32x64.
// ---------------------------------------------------------------------------
#define SAH 40
#define SBH 136

template <int OC, bool EMIT>
__global__ void __launch_bounds__(256) gemm_bf16_kernel(
    const ushort_t* __restrict__ Ahi, const ushort_t* __restrict__ Alo,
    const float* __restrict__ bias, const ushort_t* __restrict__ Bhi,
    const ushort_t* __restrict__ Blo, const float* __restrict__ R,
    float* __restrict__ Yf, ushort_t* __restrict__ Yhi,
    ushort_t* __restrict__ Ylo) {
  __shared__ __align__(16) ushort_t As[2][128 * SAH];
  __shared__ __align__(16) ushort_t Bs[2][32 * SBH];

  const int tid = threadIdx.x, lane = tid & 31, wid = tid >> 5;
  const int wm = wid >> 1, wn = wid & 1;
  const int bz = blockIdx.z;
  const int o0 = blockIdx.y * 128;
  const int t0 = blockIdx.x * 128;
  const size_t bb = (size_t)bz * NC * NHW;

  const int a_r = lane & 15, a_c = (lane >> 4) << 3;
  const int b_g = lane >> 3;
  const int b_row = ((b_g & 1) << 3) + (lane & 7);
  const int b_col = (b_g >> 1) << 3;

  // per-thread load coordinates
  const int aw_pl = tid >> 7;              // idx/512 over 2 iters handled below
  (void)aw_pl;

  float acc[2][8][4] = {};
  uint4 pa[4], pb[4];

  // ---- load helpers (macros keep coordinates in registers) ----
#define LOAD_REGS(kc)                                                        \
  {                                                                          \
    _Pragma("unroll") for (int i = 0; i < 4; i++) {                          \
      const int idx = i * 256 + tid;                                         \
      const int pl = idx >> 9, r = (idx >> 2) & 127, cc = idx & 3;           \
      pa[i] = *(const uint4*)((pl ? Alo : Ahi) + (size_t)(o0 + r) * NC +     \
                              (kc) + cc * 8);                                \
    }                                                                        \
    _Pragma("unroll") for (int i = 0; i < 4; i++) {                          \
      const int idx = i * 256 + tid;                                         \
      const int pl = idx >> 9, r = (idx >> 4) & 31, cc = idx & 15;           \
      pb[i] = *(const uint4*)((pl ? Blo : Bhi) + bb +                        \
                              (size_t)((kc) + r) * NHW + t0 + cc * 8);       \
    }                                                                        \
  }
#define STORE_SMEM()                                                         \
  {                                                                          \
    _Pragma("unroll") for (int i = 0; i < 4; i++) {                          \
      const int idx = i * 256 + tid;                                         \
      const int pl = idx >> 9, r = (idx >> 2) & 127, cc = idx & 3;           \
      *(uint4*)&As[pl][r * SAH + cc * 8] = pa[i];                            \
    }                                                                        \
    _Pragma("unroll") for (int i = 0; i < 4; i++) {                          \
      const int idx = i * 256 + tid;                                         \
      const int pl = idx >> 9, r = (idx >> 4) & 31, cc = idx & 15;           \
      *(uint4*)&Bs[pl][r * SBH + cc * 8] = pb[i];                            \
    }                                                                        \
  }

  LOAD_REGS(0);
  STORE_SMEM();
  __syncthreads();

#pragma unroll 1
  for (int chunk = 0; chunk < NC / 32; chunk++) {
    if (chunk < NC / 32 - 1) LOAD_REGS((chunk + 1) * 32);
#pragma unroll
    for (int ks = 0; ks < 2; ks++) {
      const int kb = ks * 16;
      uint32_t ah[2][4], al[2][4];
#pragma unroll
      for (int mf = 0; mf < 2; mf++) {
        const int ao = (wm * 32 + mf * 16 + a_r) * SAH + kb + a_c;
        ldsm_x4(ah[mf], smem_u32(&As[0][ao]));
        ldsm_x4(al[mf], smem_u32(&As[1][ao]));
      }
#pragma unroll
      for (int nb = 0; nb < 4; nb++) {
        uint32_t bh[4], bl[4];
        const int bo = (kb + b_row) * SBH + wn * 64 + nb * 16 + b_col;
        ldsm_x4_t(bh, smem_u32(&Bs[0][bo]));
        ldsm_x4_t(bl, smem_u32(&Bs[1][bo]));
#pragma unroll
        for (int mf = 0; mf < 2; mf++) {
          mma16816(acc[mf][2 * nb], ah[mf], &bh[0]);
          mma16816(acc[mf][2 * nb + 1], ah[mf], &bh[2]);
          mma16816(acc[mf][2 * nb], ah[mf], &bl[0]);
          mma16816(acc[mf][2 * nb + 1], ah[mf], &bl[2]);
          mma16816(acc[mf][2 * nb], al[mf], &bh[0]);
          mma16816(acc[mf][2 * nb + 1], al[mf], &bh[2]);
        }
      }
    }
    __syncthreads();
    if (chunk < NC / 32 - 1) {
      STORE_SMEM();
      __syncthreads();
    }
  }

#pragma unroll
  for (int mf = 0; mf < 2; mf++)
#pragma unroll
    for (int nf = 0; nf < 8; nf++) {
      const int o = o0 + wm * 32 + mf * 16 + (lane >> 2);
      const int t = t0 + wn * 64 + nf * 8 + ((lane & 3) << 1);
      const size_t off0 = ((size_t)bz * OC + o) * NHW + t;
      const size_t off1 = off0 + (size_t)8 * NHW;
      const float bi0 = bias[o], bi1 = bias[o + 8];
      float y0 = acc[mf][nf][0] + bi0, y1 = acc[mf][nf][1] + bi0;
      float y2 = acc[mf][nf][2] + bi1, y3 = acc[mf][nf][3] + bi1;
      if (EMIT) {
        uint32_t h01 = packbf2(y0, y1), h23 = packbf2(y2, y3);
        uint32_t l01 = packbf2(y0 - bflo_f(h01), y1 - bfhi_f(h01));
        uint32_t l23 = packbf2(y2 - bflo_f(h23), y3 - bfhi_f(h23));
        *(uint32_t*)(Yhi + off0) = h01;
        *(uint32_t*)(Yhi + off1) = h23;
        *(uint32_t*)(Ylo + off0) = l01;
        *(uint32_t*)(Ylo + off1) = l23;
      } else {
        float2 r0 = *(const float2*)(R + off0);
        float2 r1 = *(const float2*)(R + off1);
        *(float2*)(Yf + off0) = make_float2(y0 + r0.x, y1 + r0.y);
        *(float2*)(Yf + off1) = make_float2(y2 + r1.x, y3 + r1.y);
      }
    }
#undef LOAD_REGS
#undef STORE_SMEM
}

// ---------------------------------------------------------------------------
// Flash attention, m32 warp tiles. CTA: (b,h, t-tile 256); 8 warps.
// Keys streamed in 128-tiles, processed in 64-wide halves (register bound).
// smem: Q[64][SQH]x2 (persistent), K[64][AQH]x2, V[128][AVH]x2.
// ---------------------------------------------------------------------------
#define SQH 264
#define AQH 136
#define AVH 72

__global__ void __launch_bounds__(256) attn_mma_kernel(
    const ushort_t* __restrict__ qkvhi, const ushort_t* __restrict__ qkvlo,
    ushort_t* __restrict__ outhi, ushort_t* __restrict__ outlo) {
  extern __shared__ __align__(16) ushort_t smem[];
  ushort_t* Qh = smem;                 // 64*SQH
  ushort_t* Ql = Qh + 64 * SQH;
  ushort_t* Kh = Ql + 64 * SQH;        // 64*AQH
  ushort_t* Kl = Kh + 64 * AQH;
  ushort_t* Vh = Kl + 64 * AQH;        // 128*AVH
  ushort_t* Vl = Vh + 128 * AVH;

  const int tid = threadIdx.x, lane = tid & 31, warp = tid >> 5;
  const int bh_ = blockIdx.y;
  const int b = bh_ >> 3, h = bh_ & 7;
  const int t0 = blockIdx.x * 256;

  const ushort_t* qhp = qkvhi + ((size_t)b * OC3 + h * HD) * NHW;
  const ushort_t* qlp = qkvlo + ((size_t)b * OC3 + h * HD) * NHW;
  const ushort_t* khp = qhp + (size_t)NC * NHW;
  const ushort_t* klp = qlp + (size_t)NC * NHW;
  const ushort_t* vhp = qhp + (size_t)2 * NC * NHW;
  const ushort_t* vlp = qlp + (size_t)2 * NC * NHW;

  // Load Q tile [d 64][t 256], both planes
#pragma unroll
  for (int i = 0; i < 16; i++) {
    const int idx = i * 256 + tid;
    const int pl = idx >> 11, r = (idx >> 5) & 63, c = idx & 31;
    ushort_t* dst = (pl ? Ql : Qh) + r * SQH + c * 8;
    const ushort_t* src = (pl ? qlp : qhp) + (size_t)r * NHW + t0 + c * 8;
    *(uint4*)dst = *(const uint4*)src;
  }
  __syncthreads();

  const int a_kr = ((lane >> 4) << 3) + (lane & 7);
  const int a_mc = ((lane >> 3) & 1) << 3;
  const int b_g = lane >> 3;
  const int b_row = ((b_g & 1) << 3) + (lane & 7);
  const int b_col = (b_g >> 1) << 3;

  // Hoist Q hi A-fragments (m32 = 2 mf)
  uint32_t aq[2][4][4];
#pragma unroll
  for (int mf = 0; mf < 2; mf++)
#pragma unroll
    for (int k4 = 0; k4 < 4; k4++) {
      const int ao = (k4 * 16 + a_kr) * SQH + warp * 32 + mf * 16 + a_mc;
      ldsm_x4_t(aq[mf][k4], smem_u32(&Qh[ao]));
    }

  float o8[2][8][4] = {};
  float mM[2][2], lL[2][2];
#pragma unroll
  for (int mf = 0; mf < 2; mf++) {
    mM[mf][0] = -1e30f; mM[mf][1] = -1e30f;
    lL[mf][0] = 0.f; lL[mf][1] = 0.f;
  }

#pragma unroll 1
  for (int s0 = 0; s0 < NHW; s0 += 128) {
    // K tile [d][s]
#pragma unroll
    for (int i = 0; i < 8; i++) {
      const int idx = i * 256 + tid;
      const int pl = idx >> 10, r = (idx >> 4) & 63, c = idx & 15;
      ushort_t* dst = (pl ? Kl : Kh) + r * AQH + c * 8;
      const ushort_t* src = (pl ? klp : khp) + (size_t)r * NHW + s0 + c * 8;
      *(uint4*)dst = *(const uint4*)src;
    }
    // V tile transposed [s][d]
#pragma unroll
    for (int i = 0; i < 4; i++) {
      const int idx = i * 256 + tid;
      const int pl = idx >> 9, u = idx & 511;
      const int dp = u & 31, sc = u >> 5;
      const ushort_t* src = pl ? vlp : vhp;
      ushort_t* dst = pl ? Vl : Vh;
      uint4 r0 = *(const uint4*)(src + (size_t)(2 * dp) * NHW + s0 + sc * 8);
      uint4 r1 =
          *(const uint4*)(src + (size_t)(2 * dp + 1) * NHW + s0 + sc * 8);
      uint32_t q0[4] = {r0.x, r0.y, r0.z, r0.w};
      uint32_t q1[4] = {r1.x, r1.y, r1.z, r1.w};
#pragma unroll
      for (int j2 = 0; j2 < 4; j2++) {
        uint32_t a = q0[j2], bq = q1[j2];
        uint32_t w0 = (a & 0xffffu) | (bq << 16);
        uint32_t w1 = (a >> 16) | (bq & 0xffff0000u);
        const int s = sc * 8 + 2 * j2;
        *(uint32_t*)&dst[s * AVH + 2 * dp] = w0;
        *(uint32_t*)&dst[(s + 1) * AVH + 2 * dp] = w1;
      }
    }
    __syncthreads();

#pragma unroll
    for (int hf = 0; hf < 2; hf++) {
      // reload Q lo frags for this half
      uint32_t aql[2][4][4];
#pragma unroll
      for (int mf = 0; mf < 2; mf++)
#pragma unroll
        for (int k4 = 0; k4 < 4; k4++) {
          const int ao = (k4 * 16 + a_kr) * SQH + warp * 32 + mf * 16 + a_mc;
          ldsm_x4_t(aql[mf][k4], smem_u32(&Ql[ao]));
        }

      // ---- S = Q^T K over n=64 keys of this half ----
      float sacc[2][8][4] = {};
#pragma unroll
      for (int k4 = 0; k4 < 4; k4++) {
#pragma unroll
        for (int nb = 0; nb < 4; nb++) {
          uint32_t bh[4], bl[4];
          const int bo = (k4 * 16 + b_row) * AQH + hf * 64 + nb * 16 + b_col;
          ldsm_x4_t(bh, smem_u32(&Kh[bo]));
          ldsm_x4_t(bl, smem_u32(&Kl[bo]));
#pragma unroll
          for (int mf = 0; mf < 2; mf++) {
            mma16816(sacc[mf][2 * nb], aq[mf][k4], &bh[0]);
            mma16816(sacc[mf][2 * nb + 1], aq[mf][k4], &bh[2]);
            mma16816(sacc[mf][2 * nb], aq[mf][k4], &bl[0]);
            mma16816(sacc[mf][2 * nb + 1], aq[mf][k4], &bl[2]);
            mma16816(sacc[mf][2 * nb], aql[mf][k4], &bh[0]);
            mma16816(sacc[mf][2 * nb + 1], aql[mf][k4], &bh[2]);
          }
        }
      }

      // ---- online softmax + pack P + PV per mf ----
      uint32_t Ph[2][4][4], Pw[2][4][4];
#pragma unroll
      for (int mf = 0; mf < 2; mf++) {
        float mt0 = -1e30f, mt1 = -1e30f;
#pragma unroll
        for (int f = 0; f < 8; f++) {
          sacc[mf][f][0] *= 0.125f; sacc[mf][f][1] *= 0.125f;
          sacc[mf][f][2] *= 0.125f; sacc[mf][f][3] *= 0.125f;
          mt0 = fmaxf(mt0, fmaxf(sacc[mf][f][0], sacc[mf][f][1]));
          mt1 = fmaxf(mt1, fmaxf(sacc[mf][f][2], sacc[mf][f][3]));
        }
        mt0 = fmaxf(mt0, __shfl_xor_sync(0xffffffffu, mt0, 1));
        mt0 = fmaxf(mt0, __shfl_xor_sync(0xffffffffu, mt0, 2));
        mt1 = fmaxf(mt1, __shfl_xor_sync(0xffffffffu, mt1, 1));
        mt1 = fmaxf(mt1, __shfl_xor_sync(0xffffffffu, mt1, 2));
        const float mn0 = fmaxf(mM[mf][0], mt0);
        const float mn1 = fmaxf(mM[mf][1], mt1);
        const float fac0 = __expf(mM[mf][0] - mn0);
        const float fac1 = __expf(mM[mf][1] - mn1);
        mM[mf][0] = mn0; mM[mf][1] = mn1;
        float rs0 = 0.f, rs1 = 0.f;
#pragma unroll
        for (int f = 0; f < 8; f++) {
          sacc[mf][f][0] = __expf(sacc[mf][f][0] - mn0);
          sacc[mf][f][1] = __expf(sacc[mf][f][1] - mn0);
          sacc[mf][f][2] = __expf(sacc[mf][f][2] - mn1);
          sacc[mf][f][3] = __expf(sacc[mf][f][3] - mn1);
          rs0 += sacc[mf][f][0] + sacc[mf][f][1];
          rs1 += sacc[mf][f][2] + sacc[mf][f][3];
        }
        rs0 += __shfl_xor_sync(0xffffffffu, rs0, 1);
        rs0 += __shfl_xor_sync(0xffffffffu, rs0, 2);
        rs1 += __shfl_xor_sync(0xffffffffu, rs1, 1);
        rs1 += __shfl_xor_sync(0xffffffffu, rs1, 2);
        lL[mf][0] = lL[mf][0] * fac0 + rs0;
        lL[mf][1] = lL[mf][1] * fac1 + rs1;
#pragma unroll
        for (int f = 0; f < 8; f++) {
          o8[mf][f][0] *= fac0; o8[mf][f][1] *= fac0;
          o8[mf][f][2] *= fac1; o8[mf][f][3] *= fac1;
        }
        // pack P frags (S c-frags -> A frags)
#pragma unroll
        for (int f = 0; f < 8; f++) {
          const int k8 = f >> 1, sl = (f & 1) << 1;
          uint32_t h01 = packbf2(sacc[mf][f][0], sacc[mf][f][1]);
          uint32_t h23 = packbf2(sacc[mf][f][2], sacc[mf][f][3]);
          Ph[mf][k8][sl] = h01;
          Ph[mf][k8][sl + 1] = h23;
          Pw[mf][k8][sl] =
              packbf2(sacc[mf][f][0] - bflo_f(h01), sacc[mf][f][1] - bfhi_f(h01));
          Pw[mf][k8][sl + 1] =
              packbf2(sacc[mf][f][2] - bflo_f(h23), sacc[mf][f][3] - bfhi_f(h23));
        }
      }

      // ---- O += P V over k=64 keys of this half ----
#pragma unroll
      for (int k8 = 0; k8 < 4; k8++) {
#pragma unroll
        for (int nb = 0; nb < 4; nb++) {
          uint32_t vh[4], vl[4];
          const int vo = (hf * 64 + k8 * 16 + b_row) * AVH + nb * 16 + b_col;
          ldsm_x4_t(vh, smem_u32(&Vh[vo]));
          ldsm_x4_t(vl, smem_u32(&Vl[vo]));
#pragma unroll
          for (int mf = 0; mf < 2; mf++) {
            mma16816(o8[mf][2 * nb], Ph[mf][k8], &vh[0]);
            mma16816(o8[mf][2 * nb + 1], Ph[mf][k8], &vh[2]);
            mma16816(o8[mf][2 * nb], Ph[mf][k8], &vl[0]);
            mma16816(o8[mf][2 * nb + 1], Ph[mf][k8], &vl[2]);
            mma16816(o8[mf][2 * nb], Pw[mf][k8], &vh[0]);
            mma16816(o8[mf][2 * nb + 1], Pw[mf][k8], &vh[2]);
          }
        }
      }
    }
    __syncthreads();
  }

  // ---- epilogue: normalize, stage [d][t 256] f32 in Q area, emit bf16 ----
  float* Ost = (float*)Qh;  // 64 x 260 floats = 66560 B (fits in Qh+Ql)
  const float i00 = 1.f / lL[0][0], i01 = 1.f / lL[0][1];
  const float i10 = 1.f / lL[1][0], i11 = 1.f / lL[1][1];
#pragma unroll
  for (int mf = 0; mf < 2; mf++) {
    const float iv0 = mf ? i10 : i00, iv1 = mf ? i11 : i01;
    const int t = warp * 32 + mf * 16 + (lane >> 2);
#pragma unroll
    for (int f = 0; f < 8; f++) {
      const int d = f * 8 + ((lane & 3) << 1);
      Ost[d * 260 + t] = o8[mf][f][0] * iv0;
      Ost[(d + 1) * 260 + t] = o8[mf][f][1] * iv0;
      Ost[d * 260 + t + 8] = o8[mf][f][2] * iv1;
      Ost[(d + 1) * 260 + t + 8] = o8[mf][f][3] * iv1;
    }
  }
  __syncthreads();
#pragma unroll
  for (int i = 0; i < 8; i++) {
    const int idx = i * 256 + tid;
    const int r = idx >> 5, c = idx & 31;
    const float* src = &Ost[r * 260 + c * 8];
    uint32_t hu[4], lu[4];
#pragma unroll
    for (int j = 0; j < 4; j++) {
      float v0 = src[2 * j], v1 = src[2 * j + 1];
      hu[j] = packbf2(v0, v1);
      lu[j] = packbf2(v0 - bflo_f(hu[j]), v1 - bfhi_f(hu[j]));
    }
    const size_t off = ((size_t)b * NC + h * HD + r) * NHW + t0 + c * 8;
    *(uint4*)(outhi + off) = make_uint4(hu[0], hu[1], hu[2], hu[3]);
    *(uint4*)(outlo + off) = make_uint4(lu[0], lu[1], lu[2], lu[3]);
  }
}

// ---------------------------------------------------------------------------
extern "C" void kernel_launch(void* const* d_in, const int* in_sizes, int n_in,
                              void* d_out, int out_size) {
  const float* x = (const float*)d_in[0];
  const float* gn_gamma = (const float*)d_in[1];
  const float* gn_beta = (const float*)d_in[2];
  const float* qkv_w = (const float*)d_in[3];
  const float* qkv_b = (const float*)d_in[4];
  const float* proj_w = (const float*)d_in[5];
  const float* proj_b = (const float*)d_in[6];
  float* out = (float*)d_out;

  ushort_t *wqh, *wql, *wph, *wpl, *xnh, *xnl, *qh, *qlo, *ath, *atl;
  cudaGetSymbolAddress((void**)&wqh, g_wqhi);
  cudaGetSymbolAddress((void**)&wql, g_wqlo);
  cudaGetSymbolAddress((void**)&wph, g_wphi);
  cudaGetSymbolAddress((void**)&wpl, g_wplo);
  cudaGetSymbolAddress((void**)&xnh, g_xnhi);
  cudaGetSymbolAddress((void**)&xnl, g_xnlo);
  cudaGetSymbolAddress((void**)&qh, g_qkvhi);
  cudaGetSymbolAddress((void**)&qlo, g_qkvlo);
  cudaGetSymbolAddress((void**)&ath, g_atthi);
  cudaGetSymbolAddress((void**)&atl, g_attlo);

  const int ATT_SMEM =
      (2 * 64 * SQH + 2 * 64 * AQH + 2 * 128 * AVH) * (int)sizeof(ushort_t);
  cudaFuncSetAttribute(attn_mma_kernel,
                       cudaFuncAttributeMaxDynamicSharedMemorySize, ATT_SMEM);

  gn_kernel<<<NB * NG, 256>>>(x, gn_gamma, gn_beta);
  prep_w_kernel<<<(OC3 * NC + NC * NC) / 4 / 256, 256>>>(qkv_w, proj_w);
  gemm_bf16_kernel<OC3, true><<<dim3(8, 12, NB), 256>>>(
      wqh, wql, qkv_b, xnh, xnl, nullptr, nullptr, qh, qlo);
  attn_mma_kernel<<<dim3(4, NB * NHEADS), 256, ATT_SMEM>>>(qh, qlo, ath, atl);
  gemm_bf16_kernel<NC, false><<<dim3(8, 4, NB), 256>>>(
      wph, wpl, proj_b, ath, atl, x, out, nullptr, nullptr);
}